// round 2
// baseline (speedup 1.0000x reference)
#include <cuda_runtime.h>
#include <cuda_bf16.h>
#include <cstdint>

// Per-vertex valence, later overwritten in place with 1/max(valence,1).
// 4M floats = 16 MB static scratch (V = 1,000,000 in the reference).
__device__ float g_valence[4u << 20];

// ---------------------------------------------------------------------------
// Pass 1: count outgoing half-edges per vertex (float so no int->float later).
// ---------------------------------------------------------------------------
__global__ void count_kernel(const int* __restrict__ ids, int n)
{
    int i = blockIdx.x * blockDim.x + threadIdx.x;
    if (i < n) {
        atomicAdd(&g_valence[__ldg(ids + i)], 1.0f);  // emitted as RED
    }
}

// ---------------------------------------------------------------------------
// Pass 2: valence -> 1/max(valence,1), in place.
// ---------------------------------------------------------------------------
__global__ void inv_kernel(int V)
{
    int i = blockIdx.x * blockDim.x + threadIdx.x;
    if (i < V) {
        float v = g_valence[i];
        g_valence[i] = 1.0f / fmaxf(v, 1.0f);
    }
}

// ---------------------------------------------------------------------------
// Pass 3 (x NUM_PASSES): scaled scatter restricted to a vertex range so the
// live atomic accumulator region (<= 64 MB) stays L2-resident.
//   idx = e*8 + s : thread covers x[e][4s..4s+3] as one float4.
// x is streamed with an L2 evict-first policy so it doesn't evict the
// accumulator. Contributions are pre-scaled by 1/valence -> no divide pass.
// ---------------------------------------------------------------------------
__global__ void scatter_kernel(const float4* __restrict__ x4,
                               const int* __restrict__ ids,
                               float* __restrict__ out,
                               long long n_he, int vlo, int vhi)
{
    long long idx = (long long)blockIdx.x * blockDim.x + threadIdx.x;
    long long e = idx >> 3;
    if (e >= n_he) return;
    int s = (int)(idx & 7);

    int vid = __ldg(ids + e);
    if (vid < vlo || vid >= vhi) return;

    unsigned long long pol;
    asm("createpolicy.fractional.L2::evict_first.b64 %0, 1.0;" : "=l"(pol));

    float4 v;
    asm("ld.global.nc.L2::cache_hint.v4.f32 {%0, %1, %2, %3}, [%4], %5;"
        : "=f"(v.x), "=f"(v.y), "=f"(v.z), "=f"(v.w)
        : "l"(x4 + idx), "l"(pol));

    float inv = __ldg(&g_valence[vid]);  // holds 1/valence now
    v.x *= inv; v.y *= inv; v.z *= inv; v.w *= inv;

    float* dst = out + (long long)vid * 32 + s * 4;  // 16B aligned
    asm volatile("red.global.add.v4.f32 [%0], {%1, %2, %3, %4};"
                 :: "l"(dst), "f"(v.x), "f"(v.y), "f"(v.z), "f"(v.w)
                 : "memory");
}

extern "C" void kernel_launch(void* const* d_in, const int* in_sizes, int n_in,
                              void* d_out, int out_size)
{
    const float4* x4  = (const float4*)d_in[0];
    const int*    ids = (const int*)d_in[1];

    long long n_he = in_sizes[1];               // element count of vertex_ids
    int V = (int)((long long)out_size / 32);    // output is [V, 32]

    float* out = (float*)d_out;

    // Zero accumulators (d_out is poisoned before timing).
    cudaMemsetAsync(d_out, 0, (size_t)out_size * sizeof(float));
    void* valence_ptr = nullptr;
    cudaGetSymbolAddress(&valence_ptr, g_valence);
    cudaMemsetAsync(valence_ptr, 0, (size_t)V * sizeof(float));

    // Valence count + invert.
    {
        int threads = 256;
        int blocks = (int)((n_he + threads - 1) / threads);
        count_kernel<<<blocks, threads>>>(ids, (int)n_he);
        inv_kernel<<<(V + threads - 1) / threads, threads>>>(V);
    }

    // Partitioned scaled scatter: keep live accumulator range <= ~64 MB in L2.
    {
        const long long ACC_BYTES_PER_VTX = 32 * 4;           // 128 B
        const long long TARGET = 64ll << 20;                  // 64 MB
        int passes = (int)(((long long)V * ACC_BYTES_PER_VTX + TARGET - 1) / TARGET);
        if (passes < 1) passes = 1;

        long long total = n_he * 8;
        int threads = 256;
        long long blocks = (total + threads - 1) / threads;

        int vstep = (V + passes - 1) / passes;
        for (int p = 0; p < passes; p++) {
            int vlo = p * vstep;
            int vhi = vlo + vstep; if (vhi > V) vhi = V;
            scatter_kernel<<<(unsigned)blocks, threads>>>(x4, ids, out, n_he, vlo, vhi);
        }
    }
}